// round 5
// baseline (speedup 1.0000x reference)
#include <cuda_runtime.h>
#include <cuda_bf16.h>
#include <cstdint>

#define N_NODES 50000
#define N_EDGES 800000
#define DIM     128
#define LN_EPS  1e-5f

typedef unsigned long long u64;

// ---------------- device scratch ----------------
__device__ float g_h[N_NODES * DIM];
__device__ float g_buf[N_NODES * DIM];
__device__ int   g_deg[N_NODES];
__device__ int   g_off[N_NODES + 1];
__device__ int   g_cursor[N_NODES];
__device__ int2  g_edge[N_EDGES];         // {src, bit-cast edge weight}
__device__ u64   g_Wp[64 * DIM];          // K-paired weights: [k2][j] = (W[2k2][j], W[2k2+1][j])

// ---------------- f32x2 packed math helpers ----------------
__device__ __forceinline__ u64 pack2(float a, float b) {
    u64 r;
    asm("mov.b64 %0, {%1,%2};" : "=l"(r) : "f"(a), "f"(b));
    return r;
}
__device__ __forceinline__ u64 fma2(u64 x, u64 y, u64 z) {
    u64 r;
    asm("fma.rn.f32x2 %0, %1, %2, %3;" : "=l"(r) : "l"(x), "l"(y), "l"(z));
    return r;
}
__device__ __forceinline__ float2 unpack2(u64 v) {
    float2 f;
    asm("mov.b64 {%0,%1}, %2;" : "=f"(f.x), "=f"(f.y) : "l"(v));
    return f;
}

// ---------------- W repack: row-pairs over K ----------------
__global__ void pack_w_kernel(const float* __restrict__ W) {
    int i = blockIdx.x * blockDim.x + threadIdx.x;   // 0..8191
    if (i < 64 * DIM) {
        int k2 = i >> 7, j = i & 127;
        g_Wp[i] = pack2(W[(2 * k2) * DIM + j], W[(2 * k2 + 1) * DIM + j]);
    }
}

// ---------------- CSR build ----------------
__global__ void count_kernel(const int* __restrict__ eidx, int E) {
    int e = blockIdx.x * blockDim.x + threadIdx.x;
    if (e < E) atomicAdd(&g_deg[eidx[E + e]], 1);
}

__global__ void scan_kernel(int n) {
    __shared__ int wsum[32];
    int tid = threadIdx.x, lane = tid & 31, wid = tid >> 5;
    int carry = 0;
    for (int base = 0; base < n; base += 4096) {
        int i0 = base + tid * 4;
        int v0 = (i0 + 0 < n) ? g_deg[i0 + 0] : 0;
        int v1 = (i0 + 1 < n) ? g_deg[i0 + 1] : 0;
        int v2 = (i0 + 2 < n) ? g_deg[i0 + 2] : 0;
        int v3 = (i0 + 3 < n) ? g_deg[i0 + 3] : 0;
        int tsum = v0 + v1 + v2 + v3;
        int x = tsum;
        #pragma unroll
        for (int o = 1; o < 32; o <<= 1) {
            int y = __shfl_up_sync(0xffffffffu, x, o);
            if (lane >= o) x += y;
        }
        if (lane == 31) wsum[wid] = x;
        __syncthreads();
        if (wid == 0) {
            int s = wsum[lane];
            #pragma unroll
            for (int o = 1; o < 32; o <<= 1) {
                int y = __shfl_up_sync(0xffffffffu, s, o);
                if (lane >= o) s += y;
            }
            wsum[lane] = s;
        }
        __syncthreads();
        int run = carry + (x - tsum) + (wid > 0 ? wsum[wid - 1] : 0);
        if (i0 + 0 < n) { g_off[i0 + 0] = run; g_cursor[i0 + 0] = run; } run += v0;
        if (i0 + 1 < n) { g_off[i0 + 1] = run; g_cursor[i0 + 1] = run; } run += v1;
        if (i0 + 2 < n) { g_off[i0 + 2] = run; g_cursor[i0 + 2] = run; } run += v2;
        if (i0 + 3 < n) { g_off[i0 + 3] = run; g_cursor[i0 + 3] = run; }
        carry += wsum[31];
        __syncthreads();
    }
    if (tid == 0) g_off[n] = carry;
}

__global__ void fill_kernel(const int* __restrict__ eidx,
                            const float* __restrict__ ew, int E) {
    int e = blockIdx.x * blockDim.x + threadIdx.x;
    if (e < E) {
        int s = eidx[e];
        int d = eidx[E + e];
        int p = atomicAdd(&g_cursor[d], 1);
        g_edge[p] = make_int2(s, __float_as_int(ew[e]));
    }
}

// ---------------- GEMM v3: H = X @ W via K-paired f32x2 ----------------
// Block = 256 threads (8 warps), 8 rows per warp -> 64 rows/block.
// Lane l owns output cols 4l..4l+3. Accumulator (even-k, odd-k) folded at end.
__global__ void __launch_bounds__(256, 2) gemm128_kernel(
        const float* __restrict__ X, float* __restrict__ H, int nrows) {
    __shared__ u64 xs[64][64];   // [row][k2] = (x[2k2], x[2k2+1]); 32 KB
    int tid = threadIdx.x, lane = tid & 31, w = tid >> 5;
    int blockRow = blockIdx.x * 64;

    // stage 64 rows (float4 = 2 k2-pairs, layout-compatible)
    #pragma unroll
    for (int r = 0; r < 64; r += 8) {
        int row = blockRow + r + w;
        if (row < nrows)
            ((float4*)&xs[r + w][0])[lane] =
                ((const float4*)(X + (size_t)row * DIM))[lane];
    }
    __syncthreads();

    const ulonglong2* Wv = (const ulonglong2*)g_Wp;  // [k2*64 + j2]
    int myRow0 = blockRow + w * 8;

    u64 acc[8][4];
    #pragma unroll
    for (int r = 0; r < 8; ++r)
        #pragma unroll
        for (int c = 0; c < 4; ++c) acc[r][c] = 0ull;

    #pragma unroll 4
    for (int k2 = 0; k2 < 64; ++k2) {
        ulonglong2 wa = __ldg(&Wv[k2 * 64 + 2 * lane]);      // cols 4l,4l+1
        ulonglong2 wb = __ldg(&Wv[k2 * 64 + 2 * lane + 1]);  // cols 4l+2,4l+3
        #pragma unroll
        for (int r = 0; r < 8; ++r) {
            u64 a = xs[w * 8 + r][k2];                       // LDS.64 broadcast
            acc[r][0] = fma2(wa.x, a, acc[r][0]);
            acc[r][1] = fma2(wa.y, a, acc[r][1]);
            acc[r][2] = fma2(wb.x, a, acc[r][2]);
            acc[r][3] = fma2(wb.y, a, acc[r][3]);
        }
    }

    #pragma unroll
    for (int r = 0; r < 8; ++r) {
        int row = myRow0 + r;
        if (row < nrows) {
            float2 c0 = unpack2(acc[r][0]);
            float2 c1 = unpack2(acc[r][1]);
            float2 c2 = unpack2(acc[r][2]);
            float2 c3 = unpack2(acc[r][3]);
            ((float4*)(H + (size_t)row * DIM))[lane] =
                make_float4(c0.x + c0.y, c1.x + c1.y, c2.x + c2.y, c3.x + c3.y);
        }
    }
}

// ---------------- Aggregate + bias + LayerNorm + ReLU (fused) ----------------
__global__ __launch_bounds__(256) void agg_ln_relu_kernel(
        const float* __restrict__ H,
        const float* __restrict__ bias,
        const float* __restrict__ gamma,
        const float* __restrict__ beta,
        float* __restrict__ out, int nrows) {
    int w = threadIdx.x >> 5, lane = threadIdx.x & 31;
    int node = blockIdx.x * 8 + w;
    if (node >= nrows) return;

    int jb = g_off[node], je = g_off[node + 1];
    const float4* Hv = (const float4*)H;

    float4 acc = make_float4(0.f, 0.f, 0.f, 0.f);
    int j = jb;
    for (; j + 8 <= je; j += 8) {
        int2 p[8];
        #pragma unroll
        for (int u = 0; u < 8; ++u) p[u] = __ldg(&g_edge[j + u]);
        float4 hv[8];
        #pragma unroll
        for (int u = 0; u < 8; ++u)
            hv[u] = __ldg(&Hv[(size_t)p[u].x * 32 + lane]);
        #pragma unroll
        for (int u = 0; u < 8; ++u) {
            float e = __int_as_float(p[u].y);
            acc.x += e * hv[u].x; acc.y += e * hv[u].y;
            acc.z += e * hv[u].z; acc.w += e * hv[u].w;
        }
    }
    for (; j < je; ++j) {
        int2 p = __ldg(&g_edge[j]);
        float e = __int_as_float(p.y);
        float4 hv = __ldg(&Hv[(size_t)p.x * 32 + lane]);
        acc.x += e * hv.x; acc.y += e * hv.y;
        acc.z += e * hv.z; acc.w += e * hv.w;
    }

    float4 b4 = __ldg(&((const float4*)bias)[lane]);
    acc.x += b4.x; acc.y += b4.y; acc.z += b4.z; acc.w += b4.w;

    float s1 = acc.x + acc.y + acc.z + acc.w;
    float s2 = acc.x * acc.x + acc.y * acc.y + acc.z * acc.z + acc.w * acc.w;
    #pragma unroll
    for (int o = 16; o > 0; o >>= 1) {
        s1 += __shfl_xor_sync(0xffffffffu, s1, o);
        s2 += __shfl_xor_sync(0xffffffffu, s2, o);
    }
    float mu  = s1 * (1.f / 128.f);
    float var = s2 * (1.f / 128.f) - mu * mu;
    float r   = rsqrtf(var + LN_EPS);

    float4 g4 = __ldg(&((const float4*)gamma)[lane]);
    float4 e4 = __ldg(&((const float4*)beta)[lane]);
    float4 y;
    y.x = fmaxf((acc.x - mu) * r * g4.x + e4.x, 0.f);
    y.y = fmaxf((acc.y - mu) * r * g4.y + e4.y, 0.f);
    y.z = fmaxf((acc.z - mu) * r * g4.z + e4.z, 0.f);
    y.w = fmaxf((acc.w - mu) * r * g4.w + e4.w, 0.f);
    ((float4*)(out + (size_t)node * DIM))[lane] = y;
}

// ---------------- launch ----------------
extern "C" void kernel_launch(void* const* d_in, const int* in_sizes, int n_in,
                              void* d_out, int out_size) {
    const float* x    = (const float*)d_in[0];
    const int*   eidx = (const int*)d_in[1];
    const float* ew   = (const float*)d_in[2];
    const float* W1   = (const float*)d_in[3];
    const float* b1   = (const float*)d_in[4];
    const float* W2   = (const float*)d_in[5];
    const float* b2   = (const float*)d_in[6];
    const float* g1   = (const float*)d_in[7];
    const float* be1  = (const float*)d_in[8];
    const float* g2   = (const float*)d_in[9];
    const float* be2  = (const float*)d_in[10];
    float* out = (float*)d_out;

    const int N = N_NODES;
    const int E = N_EDGES;

    float *h_p, *buf_p;
    int   *deg_p;
    cudaGetSymbolAddress((void**)&h_p,   g_h);
    cudaGetSymbolAddress((void**)&buf_p, g_buf);
    cudaGetSymbolAddress((void**)&deg_p, g_deg);

    // ---- CSR build ----
    cudaMemsetAsync(deg_p, 0, N * sizeof(int));
    count_kernel<<<(E + 255) / 256, 256>>>(eidx, E);
    scan_kernel<<<1, 1024>>>(N);
    fill_kernel<<<(E + 255) / 256, 256>>>(eidx, ew, E);

    const int gemm_blocks = (N + 63) / 64;
    const int agg_blocks  = (N + 7) / 8;

    // ---- layer 1 ----
    pack_w_kernel<<<32, 256>>>(W1);
    gemm128_kernel<<<gemm_blocks, 256>>>(x, h_p, N);
    agg_ln_relu_kernel<<<agg_blocks, 256>>>(h_p, b1, g1, be1, buf_p, N);

    // ---- layer 2 ----
    pack_w_kernel<<<32, 256>>>(W2);
    gemm128_kernel<<<gemm_blocks, 256>>>(buf_p, h_p, N);
    agg_ln_relu_kernel<<<agg_blocks, 256>>>(h_p, b2, g2, be2, out, N);
}

// round 7
// speedup vs baseline: 1.2025x; 1.2025x over previous
#include <cuda_runtime.h>
#include <cuda_bf16.h>
#include <cstdint>

#define N_NODES 50000
#define N_EDGES 800000
#define DIM     128
#define LN_EPS  1e-5f

typedef unsigned int u32;

// ---------------- device scratch ----------------
__device__ float g_h[N_NODES * DIM];
__device__ float g_buf[N_NODES * DIM];
__device__ int   g_deg[N_NODES];
__device__ int   g_off[N_NODES + 1];
__device__ int   g_cursor[N_NODES];
__device__ int2  g_edge[N_EDGES];
// Fragment-ordered W for mma.m16n8k16 row.col: [hl][kc][nt][lane] -> uint2
// hl: 0=hi,1=lo ; kc: k-chunk 0..7 ; nt: n-tile 0..15 ; lane 0..31
__device__ uint2 g_Wf1[2 * 8 * 16 * 32];
__device__ uint2 g_Wf2[2 * 8 * 16 * 32];

__device__ __forceinline__ u32 pack_bf16x2(float a, float b) {
    u32 lo = (u32)__bfloat16_as_ushort(__float2bfloat16(a));
    u32 hi = (u32)__bfloat16_as_ushort(__float2bfloat16(b));
    return lo | (hi << 16);
}
__device__ __forceinline__ float bf_resid(float a) {
    return a - __bfloat162float(__float2bfloat16(a));
}

// ---------------- W -> fragment image ----------------
__global__ void conv_w_kernel(const float* __restrict__ W, uint2* __restrict__ Wf) {
    int i = blockIdx.x * blockDim.x + threadIdx.x;   // 0..8191
    if (i >= 8192) return;
    int lane = i & 31;
    int nt   = (i >> 5) & 15;
    int kc   = (i >> 9) & 7;
    int hl   = i >> 12;
    int tg = lane >> 2, tq = lane & 3;
    int n  = nt * 8 + tg;
    int kb = kc * 16 + tq * 2;
    float w0 = W[(kb + 0) * DIM + n];
    float w1 = W[(kb + 1) * DIM + n];
    float w8 = W[(kb + 8) * DIM + n];
    float w9 = W[(kb + 9) * DIM + n];
    if (hl) { w0 = bf_resid(w0); w1 = bf_resid(w1); w8 = bf_resid(w8); w9 = bf_resid(w9); }
    Wf[i] = make_uint2(pack_bf16x2(w0, w1), pack_bf16x2(w8, w9));
}

// ---------------- tensor-core GEMM: H = X @ W (bf16 hi/lo split) ----------------
// 256 threads = 8 warps; warp w computes rows [blockRow + 16w, +16) x all 128 cols.
__device__ __forceinline__ void mma16816(float* c, const u32* a, uint2 b) {
    asm volatile(
        "mma.sync.aligned.m16n8k16.row.col.f32.bf16.bf16.f32 "
        "{%0,%1,%2,%3}, {%4,%5,%6,%7}, {%8,%9}, {%0,%1,%2,%3};"
        : "+f"(c[0]), "+f"(c[1]), "+f"(c[2]), "+f"(c[3])
        : "r"(a[0]), "r"(a[1]), "r"(a[2]), "r"(a[3]), "r"(b.x), "r"(b.y));
}

__global__ void __launch_bounds__(256, 2) gemm_mma_kernel(
        const float* __restrict__ X, const uint2* __restrict__ Wf,
        float* __restrict__ H, int nrows) {
    int tid = threadIdx.x, w = tid >> 5, lane = tid & 31;
    int tg = lane >> 2, tq = lane & 3;
    int rowBase = blockIdx.x * 128 + w * 16;
    int r0 = rowBase + tg, r1 = r0 + 8;
    int r0c = min(r0, nrows - 1), r1c = min(r1, nrows - 1);
    const float* X0 = X + (size_t)r0c * DIM;
    const float* X1 = X + (size_t)r1c * DIM;

    float acc[16][4];
    #pragma unroll
    for (int nt = 0; nt < 16; ++nt)
        #pragma unroll
        for (int c = 0; c < 4; ++c) acc[nt][c] = 0.f;

    #pragma unroll
    for (int kc = 0; kc < 8; ++kc) {
        int c0 = kc * 16 + tq * 2;
        float2 x00 = *(const float2*)(X0 + c0);
        float2 x01 = *(const float2*)(X0 + c0 + 8);
        float2 x10 = *(const float2*)(X1 + c0);
        float2 x11 = *(const float2*)(X1 + c0 + 8);
        u32 ahi[4], alo[4];
        ahi[0] = pack_bf16x2(x00.x, x00.y);
        ahi[1] = pack_bf16x2(x10.x, x10.y);
        ahi[2] = pack_bf16x2(x01.x, x01.y);
        ahi[3] = pack_bf16x2(x11.x, x11.y);
        alo[0] = pack_bf16x2(bf_resid(x00.x), bf_resid(x00.y));
        alo[1] = pack_bf16x2(bf_resid(x10.x), bf_resid(x10.y));
        alo[2] = pack_bf16x2(bf_resid(x01.x), bf_resid(x01.y));
        alo[3] = pack_bf16x2(bf_resid(x11.x), bf_resid(x11.y));

        const uint2* bh = Wf + ((size_t)(0 * 8 + kc) * 16) * 32 + lane;
        const uint2* bl = Wf + ((size_t)(1 * 8 + kc) * 16) * 32 + lane;
        #pragma unroll
        for (int nt = 0; nt < 16; ++nt) {
            uint2 bhv = __ldg(bh + nt * 32);
            uint2 blv = __ldg(bl + nt * 32);
            mma16816(acc[nt], ahi, bhv);
            mma16816(acc[nt], ahi, blv);
            mma16816(acc[nt], alo, bhv);
        }
    }

    // store: c0,c1 -> row r0, cols nt*8 + tq*2 ; c2,c3 -> row r1
    #pragma unroll
    for (int nt = 0; nt < 16; ++nt) {
        int col = nt * 8 + tq * 2;
        if (r0 < nrows)
            *(float2*)(H + (size_t)r0 * DIM + col) = make_float2(acc[nt][0], acc[nt][1]);
        if (r1 < nrows)
            *(float2*)(H + (size_t)r1 * DIM + col) = make_float2(acc[nt][2], acc[nt][3]);
    }
}

// ---------------- CSR build ----------------
__global__ void count_kernel(const int* __restrict__ eidx, int E) {
    int e = blockIdx.x * blockDim.x + threadIdx.x;
    if (e < E) atomicAdd(&g_deg[eidx[E + e]], 1);
}

__global__ void scan_kernel(int n) {
    __shared__ int wsum[32];
    int tid = threadIdx.x, lane = tid & 31, wid = tid >> 5;
    int carry = 0;
    for (int base = 0; base < n; base += 4096) {
        int i0 = base + tid * 4;
        int v0 = (i0 + 0 < n) ? g_deg[i0 + 0] : 0;
        int v1 = (i0 + 1 < n) ? g_deg[i0 + 1] : 0;
        int v2 = (i0 + 2 < n) ? g_deg[i0 + 2] : 0;
        int v3 = (i0 + 3 < n) ? g_deg[i0 + 3] : 0;
        int tsum = v0 + v1 + v2 + v3;
        int x = tsum;
        #pragma unroll
        for (int o = 1; o < 32; o <<= 1) {
            int y = __shfl_up_sync(0xffffffffu, x, o);
            if (lane >= o) x += y;
        }
        if (lane == 31) wsum[wid] = x;
        __syncthreads();
        if (wid == 0) {
            int s = wsum[lane];
            #pragma unroll
            for (int o = 1; o < 32; o <<= 1) {
                int y = __shfl_up_sync(0xffffffffu, s, o);
                if (lane >= o) s += y;
            }
            wsum[lane] = s;
        }
        __syncthreads();
        int run = carry + (x - tsum) + (wid > 0 ? wsum[wid - 1] : 0);
        if (i0 + 0 < n) { g_off[i0 + 0] = run; g_cursor[i0 + 0] = run; } run += v0;
        if (i0 + 1 < n) { g_off[i0 + 1] = run; g_cursor[i0 + 1] = run; } run += v1;
        if (i0 + 2 < n) { g_off[i0 + 2] = run; g_cursor[i0 + 2] = run; } run += v2;
        if (i0 + 3 < n) { g_off[i0 + 3] = run; g_cursor[i0 + 3] = run; }
        carry += wsum[31];
        __syncthreads();
    }
    if (tid == 0) g_off[n] = carry;
}

__global__ void fill_kernel(const int* __restrict__ eidx,
                            const float* __restrict__ ew, int E) {
    int e = blockIdx.x * blockDim.x + threadIdx.x;
    if (e < E) {
        int s = eidx[e];
        int d = eidx[E + e];
        int p = atomicAdd(&g_cursor[d], 1);
        g_edge[p] = make_int2(s, __float_as_int(ew[e]));
    }
}

// ---------------- Aggregate + bias + LayerNorm + ReLU (fused) ----------------
__global__ __launch_bounds__(256) void agg_ln_relu_kernel(
        const float* __restrict__ H,
        const float* __restrict__ bias,
        const float* __restrict__ gamma,
        const float* __restrict__ beta,
        float* __restrict__ out, int nrows) {
    int w = threadIdx.x >> 5, lane = threadIdx.x & 31;
    int node = blockIdx.x * 8 + w;
    if (node >= nrows) return;

    int jb = g_off[node], je = g_off[node + 1];
    const float4* Hv = (const float4*)H;

    float4 acc = make_float4(0.f, 0.f, 0.f, 0.f);
    int j = jb;
    for (; j + 8 <= je; j += 8) {
        int2 p[8];
        #pragma unroll
        for (int u = 0; u < 8; ++u) p[u] = __ldg(&g_edge[j + u]);
        float4 hv[8];
        #pragma unroll
        for (int u = 0; u < 8; ++u)
            hv[u] = __ldg(&Hv[(size_t)p[u].x * 32 + lane]);
        #pragma unroll
        for (int u = 0; u < 8; ++u) {
            float e = __int_as_float(p[u].y);
            acc.x += e * hv[u].x; acc.y += e * hv[u].y;
            acc.z += e * hv[u].z; acc.w += e * hv[u].w;
        }
    }
    for (; j < je; ++j) {
        int2 p = __ldg(&g_edge[j]);
        float e = __int_as_float(p.y);
        float4 hv = __ldg(&Hv[(size_t)p.x * 32 + lane]);
        acc.x += e * hv.x; acc.y += e * hv.y;
        acc.z += e * hv.z; acc.w += e * hv.w;
    }

    float4 b4 = __ldg(&((const float4*)bias)[lane]);
    acc.x += b4.x; acc.y += b4.y; acc.z += b4.z; acc.w += b4.w;

    float s1 = acc.x + acc.y + acc.z + acc.w;
    float s2 = acc.x * acc.x + acc.y * acc.y + acc.z * acc.z + acc.w * acc.w;
    #pragma unroll
    for (int o = 16; o > 0; o >>= 1) {
        s1 += __shfl_xor_sync(0xffffffffu, s1, o);
        s2 += __shfl_xor_sync(0xffffffffu, s2, o);
    }
    float mu  = s1 * (1.f / 128.f);
    float var = s2 * (1.f / 128.f) - mu * mu;
    float r   = rsqrtf(var + LN_EPS);

    float4 g4 = __ldg(&((const float4*)gamma)[lane]);
    float4 e4 = __ldg(&((const float4*)beta)[lane]);
    float4 y;
    y.x = fmaxf((acc.x - mu) * r * g4.x + e4.x, 0.f);
    y.y = fmaxf((acc.y - mu) * r * g4.y + e4.y, 0.f);
    y.z = fmaxf((acc.z - mu) * r * g4.z + e4.z, 0.f);
    y.w = fmaxf((acc.w - mu) * r * g4.w + e4.w, 0.f);
    ((float4*)(out + (size_t)node * DIM))[lane] = y;
}

// ---------------- launch ----------------
extern "C" void kernel_launch(void* const* d_in, const int* in_sizes, int n_in,
                              void* d_out, int out_size) {
    const float* x    = (const float*)d_in[0];
    const int*   eidx = (const int*)d_in[1];
    const float* ew   = (const float*)d_in[2];
    const float* W1   = (const float*)d_in[3];
    const float* b1   = (const float*)d_in[4];
    const float* W2   = (const float*)d_in[5];
    const float* b2   = (const float*)d_in[6];
    const float* g1   = (const float*)d_in[7];
    const float* be1  = (const float*)d_in[8];
    const float* g2   = (const float*)d_in[9];
    const float* be2  = (const float*)d_in[10];
    float* out = (float*)d_out;

    const int N = N_NODES;
    const int E = N_EDGES;

    float *h_p, *buf_p;
    int   *deg_p;
    uint2 *wf1, *wf2;
    cudaGetSymbolAddress((void**)&h_p,   g_h);
    cudaGetSymbolAddress((void**)&buf_p, g_buf);
    cudaGetSymbolAddress((void**)&deg_p, g_deg);
    cudaGetSymbolAddress((void**)&wf1,   g_Wf1);
    cudaGetSymbolAddress((void**)&wf2,   g_Wf2);

    // ---- CSR build ----
    cudaMemsetAsync(deg_p, 0, N * sizeof(int));
    count_kernel<<<(E + 255) / 256, 256>>>(eidx, E);
    scan_kernel<<<1, 1024>>>(N);
    fill_kernel<<<(E + 255) / 256, 256>>>(eidx, ew, E);

    const int tiles      = (N + 127) / 128;
    const int agg_blocks = (N + 7) / 8;

    // ---- W fragment images ----
    conv_w_kernel<<<32, 256>>>(W1, wf1);
    conv_w_kernel<<<32, 256>>>(W2, wf2);

    // ---- layer 1 ----
    gemm_mma_kernel<<<tiles, 256>>>(x, wf1, h_p, N);
    agg_ln_relu_kernel<<<agg_blocks, 256>>>(h_p, b1, g1, be1, buf_p, N);

    // ---- layer 2 ----
    gemm_mma_kernel<<<tiles, 256>>>(buf_p, wf2, h_p, N);
    agg_ln_relu_kernel<<<agg_blocks, 256>>>(h_p, b2, g2, be2, out, N);
}

// round 8
// speedup vs baseline: 1.3616x; 1.1323x over previous
#include <cuda_runtime.h>
#include <cuda_bf16.h>
#include <cuda_fp16.h>
#include <cstdint>

#define N_NODES 50000
#define N_EDGES 800000
#define DIM     128
#define LN_EPS  1e-5f

typedef unsigned int u32;

// ---------------- device scratch ----------------
__device__ __half g_h[N_NODES * DIM];     // post-GEMM features (fp16!)
__device__ float  g_buf[N_NODES * DIM];   // layer-1 output (fp32, GEMM2 input)
__device__ int    g_deg[N_NODES];
__device__ int    g_off[N_NODES + 1];
__device__ int    g_cursor[N_NODES];
__device__ int2   g_edge[N_EDGES];
// Fragment-ordered W for mma.m16n8k16 row.col: [hl][kc][nt][lane] -> uint2
__device__ uint2  g_Wf1[2 * 8 * 16 * 32];
__device__ uint2  g_Wf2[2 * 8 * 16 * 32];

__device__ __forceinline__ u32 pack_bf16x2(float a, float b) {
    u32 lo = (u32)__bfloat16_as_ushort(__float2bfloat16(a));
    u32 hi = (u32)__bfloat16_as_ushort(__float2bfloat16(b));
    return lo | (hi << 16);
}
__device__ __forceinline__ float bf_resid(float a) {
    return a - __bfloat162float(__float2bfloat16(a));
}
__device__ __forceinline__ u32 pack_half2(float a, float b) {
    __half2 h = __float22half2_rn(make_float2(a, b));
    return *(u32*)&h;
}

// ---------------- W -> fragment image ----------------
__global__ void conv_w_kernel(const float* __restrict__ W, uint2* __restrict__ Wf) {
    int i = blockIdx.x * blockDim.x + threadIdx.x;   // 0..8191
    if (i >= 8192) return;
    int lane = i & 31;
    int nt   = (i >> 5) & 15;
    int kc   = (i >> 9) & 7;
    int hl   = i >> 12;
    int tg = lane >> 2, tq = lane & 3;
    int n  = nt * 8 + tg;
    int kb = kc * 16 + tq * 2;
    float w0 = W[(kb + 0) * DIM + n];
    float w1 = W[(kb + 1) * DIM + n];
    float w8 = W[(kb + 8) * DIM + n];
    float w9 = W[(kb + 9) * DIM + n];
    if (hl) { w0 = bf_resid(w0); w1 = bf_resid(w1); w8 = bf_resid(w8); w9 = bf_resid(w9); }
    Wf[i] = make_uint2(pack_bf16x2(w0, w1), pack_bf16x2(w8, w9));
}

// ---------------- tensor-core GEMM: H(fp16) = X @ W (bf16 hi/lo split) ----------------
__device__ __forceinline__ void mma16816(float* c, const u32* a, uint2 b) {
    asm volatile(
        "mma.sync.aligned.m16n8k16.row.col.f32.bf16.bf16.f32 "
        "{%0,%1,%2,%3}, {%4,%5,%6,%7}, {%8,%9}, {%0,%1,%2,%3};"
        : "+f"(c[0]), "+f"(c[1]), "+f"(c[2]), "+f"(c[3])
        : "r"(a[0]), "r"(a[1]), "r"(a[2]), "r"(a[3]), "r"(b.x), "r"(b.y));
}

__global__ void __launch_bounds__(256, 2) gemm_mma_kernel(
        const float* __restrict__ X, const uint2* __restrict__ Wf,
        u32* __restrict__ Hh, int nrows) {
    int tid = threadIdx.x, w = tid >> 5, lane = tid & 31;
    int tg = lane >> 2, tq = lane & 3;
    int rowBase = blockIdx.x * 128 + w * 16;
    int r0 = rowBase + tg, r1 = r0 + 8;
    int r0c = min(r0, nrows - 1), r1c = min(r1, nrows - 1);
    const float* X0 = X + (size_t)r0c * DIM;
    const float* X1 = X + (size_t)r1c * DIM;

    float acc[16][4];
    #pragma unroll
    for (int nt = 0; nt < 16; ++nt)
        #pragma unroll
        for (int c = 0; c < 4; ++c) acc[nt][c] = 0.f;

    #pragma unroll
    for (int kc = 0; kc < 8; ++kc) {
        int c0 = kc * 16 + tq * 2;
        float2 x00 = *(const float2*)(X0 + c0);
        float2 x01 = *(const float2*)(X0 + c0 + 8);
        float2 x10 = *(const float2*)(X1 + c0);
        float2 x11 = *(const float2*)(X1 + c0 + 8);
        u32 ahi[4], alo[4];
        ahi[0] = pack_bf16x2(x00.x, x00.y);
        ahi[1] = pack_bf16x2(x10.x, x10.y);
        ahi[2] = pack_bf16x2(x01.x, x01.y);
        ahi[3] = pack_bf16x2(x11.x, x11.y);
        alo[0] = pack_bf16x2(bf_resid(x00.x), bf_resid(x00.y));
        alo[1] = pack_bf16x2(bf_resid(x10.x), bf_resid(x10.y));
        alo[2] = pack_bf16x2(bf_resid(x01.x), bf_resid(x01.y));
        alo[3] = pack_bf16x2(bf_resid(x11.x), bf_resid(x11.y));

        const uint2* bh = Wf + ((size_t)(0 * 8 + kc) * 16) * 32 + lane;
        const uint2* bl = Wf + ((size_t)(1 * 8 + kc) * 16) * 32 + lane;
        #pragma unroll
        for (int nt = 0; nt < 16; ++nt) {
            uint2 bhv = __ldg(bh + nt * 32);
            uint2 blv = __ldg(bl + nt * 32);
            mma16816(acc[nt], ahi, bhv);
            mma16816(acc[nt], ahi, blv);
            mma16816(acc[nt], alo, bhv);
        }
    }

    // store fp16: one u32 (half2) per row per nt at col nt*8 + tq*2
    #pragma unroll
    for (int nt = 0; nt < 16; ++nt) {
        int col = nt * 8 + tq * 2;
        if (r0 < nrows)
            Hh[(size_t)r0 * 64 + (col >> 1)] = pack_half2(acc[nt][0], acc[nt][1]);
        if (r1 < nrows)
            Hh[(size_t)r1 * 64 + (col >> 1)] = pack_half2(acc[nt][2], acc[nt][3]);
    }
}

// ---------------- CSR build ----------------
__global__ void count_kernel(const int* __restrict__ eidx, int E) {
    int e = blockIdx.x * blockDim.x + threadIdx.x;
    if (e < E) atomicAdd(&g_deg[eidx[E + e]], 1);
}

__global__ void scan_kernel(int n) {
    __shared__ int wsum[32];
    int tid = threadIdx.x, lane = tid & 31, wid = tid >> 5;
    int carry = 0;
    for (int base = 0; base < n; base += 4096) {
        int i0 = base + tid * 4;
        int v0 = (i0 + 0 < n) ? g_deg[i0 + 0] : 0;
        int v1 = (i0 + 1 < n) ? g_deg[i0 + 1] : 0;
        int v2 = (i0 + 2 < n) ? g_deg[i0 + 2] : 0;
        int v3 = (i0 + 3 < n) ? g_deg[i0 + 3] : 0;
        int tsum = v0 + v1 + v2 + v3;
        int x = tsum;
        #pragma unroll
        for (int o = 1; o < 32; o <<= 1) {
            int y = __shfl_up_sync(0xffffffffu, x, o);
            if (lane >= o) x += y;
        }
        if (lane == 31) wsum[wid] = x;
        __syncthreads();
        if (wid == 0) {
            int s = wsum[lane];
            #pragma unroll
            for (int o = 1; o < 32; o <<= 1) {
                int y = __shfl_up_sync(0xffffffffu, s, o);
                if (lane >= o) s += y;
            }
            wsum[lane] = s;
        }
        __syncthreads();
        int run = carry + (x - tsum) + (wid > 0 ? wsum[wid - 1] : 0);
        if (i0 + 0 < n) { g_off[i0 + 0] = run; g_cursor[i0 + 0] = run; } run += v0;
        if (i0 + 1 < n) { g_off[i0 + 1] = run; g_cursor[i0 + 1] = run; } run += v1;
        if (i0 + 2 < n) { g_off[i0 + 2] = run; g_cursor[i0 + 2] = run; } run += v2;
        if (i0 + 3 < n) { g_off[i0 + 3] = run; g_cursor[i0 + 3] = run; }
        carry += wsum[31];
        __syncthreads();
    }
    if (tid == 0) g_off[n] = carry;
}

__global__ void fill_kernel(const int* __restrict__ eidx,
                            const float* __restrict__ ew, int E) {
    int e = blockIdx.x * blockDim.x + threadIdx.x;
    if (e < E) {
        int s = eidx[e];
        int d = eidx[E + e];
        int p = atomicAdd(&g_cursor[d], 1);
        g_edge[p] = make_int2(s, __float_as_int(ew[e]));
    }
}

// ---------------- Aggregate(fp16 gather) + bias + LayerNorm + ReLU ----------------
__global__ __launch_bounds__(256) void agg_ln_relu_kernel(
        const u32* __restrict__ Hh,
        const float* __restrict__ bias,
        const float* __restrict__ gamma,
        const float* __restrict__ beta,
        float* __restrict__ out, int nrows) {
    int w = threadIdx.x >> 5, lane = threadIdx.x & 31;
    int node = blockIdx.x * 8 + w;
    if (node >= nrows) return;

    int jb = g_off[node], je = g_off[node + 1];
    const uint2* Hv = (const uint2*)Hh;   // 4 halves per uint2; lane owns cols 4l..4l+3

    float4 acc = make_float4(0.f, 0.f, 0.f, 0.f);
    int j = jb;
    for (; j + 8 <= je; j += 8) {
        int2 p[8];
        #pragma unroll
        for (int u = 0; u < 8; ++u) p[u] = __ldg(&g_edge[j + u]);
        uint2 hv[8];
        #pragma unroll
        for (int u = 0; u < 8; ++u)
            hv[u] = __ldg(&Hv[(size_t)p[u].x * 32 + lane]);
        #pragma unroll
        for (int u = 0; u < 8; ++u) {
            float e = __int_as_float(p[u].y);
            float2 f01 = __half22float2(*(__half2*)&hv[u].x);
            float2 f23 = __half22float2(*(__half2*)&hv[u].y);
            acc.x += e * f01.x; acc.y += e * f01.y;
            acc.z += e * f23.x; acc.w += e * f23.y;
        }
    }
    for (; j < je; ++j) {
        int2 p = __ldg(&g_edge[j]);
        float e = __int_as_float(p.y);
        uint2 hv = __ldg(&Hv[(size_t)p.x * 32 + lane]);
        float2 f01 = __half22float2(*(__half2*)&hv.x);
        float2 f23 = __half22float2(*(__half2*)&hv.y);
        acc.x += e * f01.x; acc.y += e * f01.y;
        acc.z += e * f23.x; acc.w += e * f23.y;
    }

    float4 b4 = __ldg(&((const float4*)bias)[lane]);
    acc.x += b4.x; acc.y += b4.y; acc.z += b4.z; acc.w += b4.w;

    float s1 = acc.x + acc.y + acc.z + acc.w;
    float s2 = acc.x * acc.x + acc.y * acc.y + acc.z * acc.z + acc.w * acc.w;
    #pragma unroll
    for (int o = 16; o > 0; o >>= 1) {
        s1 += __shfl_xor_sync(0xffffffffu, s1, o);
        s2 += __shfl_xor_sync(0xffffffffu, s2, o);
    }
    float mu  = s1 * (1.f / 128.f);
    float var = s2 * (1.f / 128.f) - mu * mu;
    float r   = rsqrtf(var + LN_EPS);

    float4 g4 = __ldg(&((const float4*)gamma)[lane]);
    float4 e4 = __ldg(&((const float4*)beta)[lane]);
    float4 y;
    y.x = fmaxf((acc.x - mu) * r * g4.x + e4.x, 0.f);
    y.y = fmaxf((acc.y - mu) * r * g4.y + e4.y, 0.f);
    y.z = fmaxf((acc.z - mu) * r * g4.z + e4.z, 0.f);
    y.w = fmaxf((acc.w - mu) * r * g4.w + e4.w, 0.f);
    ((float4*)(out + (size_t)node * DIM))[lane] = y;
}

// ---------------- launch ----------------
extern "C" void kernel_launch(void* const* d_in, const int* in_sizes, int n_in,
                              void* d_out, int out_size) {
    const float* x    = (const float*)d_in[0];
    const int*   eidx = (const int*)d_in[1];
    const float* ew   = (const float*)d_in[2];
    const float* W1   = (const float*)d_in[3];
    const float* b1   = (const float*)d_in[4];
    const float* W2   = (const float*)d_in[5];
    const float* b2   = (const float*)d_in[6];
    const float* g1   = (const float*)d_in[7];
    const float* be1  = (const float*)d_in[8];
    const float* g2   = (const float*)d_in[9];
    const float* be2  = (const float*)d_in[10];
    float* out = (float*)d_out;

    const int N = N_NODES;
    const int E = N_EDGES;

    u32   *h_p;
    float *buf_p;
    int   *deg_p;
    uint2 *wf1, *wf2;
    cudaGetSymbolAddress((void**)&h_p,   g_h);
    cudaGetSymbolAddress((void**)&buf_p, g_buf);
    cudaGetSymbolAddress((void**)&deg_p, g_deg);
    cudaGetSymbolAddress((void**)&wf1,   g_Wf1);
    cudaGetSymbolAddress((void**)&wf2,   g_Wf2);

    // ---- CSR build ----
    cudaMemsetAsync(deg_p, 0, N * sizeof(int));
    count_kernel<<<(E + 255) / 256, 256>>>(eidx, E);
    scan_kernel<<<1, 1024>>>(N);
    fill_kernel<<<(E + 255) / 256, 256>>>(eidx, ew, E);

    const int tiles      = (N + 127) / 128;
    const int agg_blocks = (N + 7) / 8;

    // ---- W fragment images ----
    conv_w_kernel<<<32, 256>>>(W1, wf1);
    conv_w_kernel<<<32, 256>>>(W2, wf2);

    // ---- layer 1 ----
    gemm_mma_kernel<<<tiles, 256>>>(x, wf1, h_p, N);
    agg_ln_relu_kernel<<<agg_blocks, 256>>>(h_p, b1, g1, be1, buf_p, N);

    // ---- layer 2 ----
    gemm_mma_kernel<<<tiles, 256>>>(buf_p, wf2, h_p, N);
    agg_ln_relu_kernel<<<agg_blocks, 256>>>(h_p, b2, g2, be2, out, N);
}